// round 1
// baseline (speedup 1.0000x reference)
#include <cuda_runtime.h>
#include <cstdint>

// ---------------------------------------------------------------------------
// Encoder_35064113004946: 2x (EdgeConv -> Conv1d(k=5,pad=2)+ReLU+MaxPool1d(2))
//
// EdgeConv trick: cat[x_i, x_j - x_i] @ W = x_i @ W_top + (x_j - x_i) @ W_bot
//   => per-node A = X@W_top, B = X@W_bot; per-edge msg = relu(A[d]+B[s]-B[d]+b)
//   => segment_max == atomicMax(float-as-int) into 0-initialized out (msgs>=0)
// Conv1d+pool: GEMM over K = 5*256 with shifted-row A gather, relu+maxpool
//   fused in epilogue (pooled row pairs are adjacent rows of the same thread).
// ---------------------------------------------------------------------------

#define T_      128
#define F_      128
#define H_      256
#define M0      32768          // B*N*T nodes, layer 0
#define E0      262144
#define M1      16384          // after pool /2
#define E1      131072
#define MOUT    8192

// scratch layout (floats)
#define OFF_X0     0
#define SZ_X0      (M0 * F_)          // 4194304
#define OFF_AB0    (OFF_X0 + SZ_X0)
#define SZ_AB0     (M0 * 512)         // 16777216
#define OFF_OUT0   (OFF_AB0 + SZ_AB0)
#define SZ_OUT0    (M0 * 256)         // 8388608
#define OFF_X1     (OFF_OUT0 + SZ_OUT0)
#define SZ_X1      (M1 * 256)         // 4194304
#define OFF_AB1    (OFF_X1 + SZ_X1)
#define SZ_AB1     (M1 * 512)         // 8388608
#define OFF_OUT1   (OFF_AB1 + SZ_AB1)
#define SZ_OUT1    (M1 * 256)         // 4194304
#define OFF_WCAT0  (OFF_OUT1 + SZ_OUT1)
#define SZ_WCAT0   (128 * 512)        // 65536
#define OFF_WCAT1  (OFF_WCAT0 + SZ_WCAT0)
#define SZ_WCAT1   (256 * 512)        // 131072
#define OFF_WT0    (OFF_WCAT1 + SZ_WCAT1)
#define SZ_WT      (1280 * 256)       // 327680
#define OFF_WT1    (OFF_WT0 + SZ_WT)
#define SCRATCH_TOTAL (OFF_WT1 + SZ_WT)   // 46989312 floats ~ 188 MB

__device__ float g_scratch[SCRATCH_TOTAL];

// ---------------------------------------------------------------------------
// input permute: data[T,B,N,F] -> x0[(b*32+n)*128 + t, f]
__global__ void permute_in(const float* __restrict__ data, float* __restrict__ x0) {
    int idx = blockIdx.x * 256 + threadIdx.x;       // over M0*F_
    int f    = idx & 127;
    int node = idx >> 7;
    int t    = node & 127;
    int bn   = node >> 7;
    int b    = bn >> 5;
    int n    = bn & 31;
    x0[idx] = data[(((t * 8 + b) * 32 + n) << 7) + f];
}

// ---------------------------------------------------------------------------
// weight prep: Wcat = [W_top | W_bot] (K x 512); Wt[(k*256+i)*256+o] = Wc[o,i,k]
__global__ void prep_weights(const float* __restrict__ W0, const float* __restrict__ W1,
                             const float* __restrict__ Wc0, const float* __restrict__ Wc1,
                             float* __restrict__ Wcat0, float* __restrict__ Wcat1,
                             float* __restrict__ Wt0, float* __restrict__ Wt1) {
    int idx = blockIdx.x * 256 + threadIdx.x;
    if (idx < 65536) {
        int f = idx >> 9, h = idx & 511;
        Wcat0[idx] = (h < 256) ? W0[f * 256 + h] : W0[(128 + f) * 256 + (h - 256)];
        return;
    }
    idx -= 65536;
    if (idx < 131072) {
        int i = idx >> 9, h = idx & 511;
        Wcat1[idx] = (h < 256) ? W1[i * 256 + h] : W1[(256 + i) * 256 + (h - 256)];
        return;
    }
    idx -= 131072;
    if (idx < 327680) {
        int kk = idx >> 8, o = idx & 255;
        int k = kk >> 8, i = kk & 255;
        Wt0[idx] = Wc0[(o * 256 + i) * 5 + k];
        return;
    }
    idx -= 327680;
    if (idx < 327680) {
        int kk = idx >> 8, o = idx & 255;
        int k = kk >> 8, i = kk & 255;
        Wt1[idx] = Wc1[(o * 256 + i) * 5 + k];
    }
}

// ---------------------------------------------------------------------------
__global__ void zero_kernel(float4* __restrict__ p) {
    p[blockIdx.x * 256 + threadIdx.x] = make_float4(0.f, 0.f, 0.f, 0.f);
}

// ---------------------------------------------------------------------------
// plain SGEMM: C[M,N] = A[M,K] @ B[K,N]; M%128==0, N%128==0, K%16==0
__global__ __launch_bounds__(256, 2)
void sgemm128(const float* __restrict__ A, const float* __restrict__ B,
              float* __restrict__ C, int N, int K) {
    __shared__ float As[16][128];
    __shared__ float Bs[16][128];
    int tid = threadIdx.x;
    int bm = blockIdx.y * 128;
    int bn = blockIdx.x * 128;
    int a_row = tid >> 2;
    int a_col = (tid & 3) << 2;
    int b_row = tid >> 5;
    int b_col = (tid & 31) << 2;
    int ty = tid >> 4, tx = tid & 15;
    float acc[8][8] = {};

    for (int k0 = 0; k0 < K; k0 += 16) {
#pragma unroll
        for (int rr = 0; rr < 2; rr++) {
            int row = a_row + rr * 64;
            float4 v = *(const float4*)(A + (size_t)(bm + row) * K + k0 + a_col);
            As[a_col + 0][row] = v.x; As[a_col + 1][row] = v.y;
            As[a_col + 2][row] = v.z; As[a_col + 3][row] = v.w;
        }
#pragma unroll
        for (int rr = 0; rr < 2; rr++) {
            int row = b_row + rr * 8;
            *(float4*)&Bs[row][b_col] = *(const float4*)(B + (size_t)(k0 + row) * N + bn + b_col);
        }
        __syncthreads();
#pragma unroll
        for (int k = 0; k < 16; k++) {
            float ra[8], rb[8];
            *(float4*)&ra[0] = *(float4*)&As[k][ty * 8];
            *(float4*)&ra[4] = *(float4*)&As[k][ty * 8 + 4];
            *(float4*)&rb[0] = *(float4*)&Bs[k][tx * 8];
            *(float4*)&rb[4] = *(float4*)&Bs[k][tx * 8 + 4];
#pragma unroll
            for (int i = 0; i < 8; i++)
#pragma unroll
                for (int j = 0; j < 8; j++)
                    acc[i][j] += ra[i] * rb[j];
        }
        __syncthreads();
    }
#pragma unroll
    for (int i = 0; i < 8; i++) {
        int row = bm + ty * 8 + i;
        float4 v0 = make_float4(acc[i][0], acc[i][1], acc[i][2], acc[i][3]);
        float4 v1 = make_float4(acc[i][4], acc[i][5], acc[i][6], acc[i][7]);
        *(float4*)(C + (size_t)row * N + bn + tx * 8) = v0;
        *(float4*)(C + (size_t)row * N + bn + tx * 8 + 4) = v1;
    }
}

// ---------------------------------------------------------------------------
// edge aggregation: out[dst] = max(out[dst], relu(A[dst]+B[src]-B[dst]+bias))
// AB: [nodes, 512], A in cols [0,256), B in cols [256,512). out pre-zeroed.
__global__ void edge_agg(const int* __restrict__ ei, int E,
                         const float* __restrict__ AB,
                         const float* __restrict__ bias,
                         float* __restrict__ out) {
    int warp = (blockIdx.x * blockDim.x + threadIdx.x) >> 5;
    if (warp >= E) return;
    int lane = threadIdx.x & 31;
    int src = __ldg(ei + warp);
    int dst = __ldg(ei + E + warp);
    const float* basd = AB + (size_t)dst * 512;
    const float* bass = AB + (size_t)src * 512;
    int* po = (int*)(out + (size_t)dst * 256);
#pragma unroll
    for (int h = 0; h < 2; h++) {
        int c = lane * 4 + h * 128;
        float4 a  = *(const float4*)(basd + c);
        float4 bd = *(const float4*)(basd + 256 + c);
        float4 bs = *(const float4*)(bass + 256 + c);
        float4 bb = *(const float4*)(bias + c);
        float v0 = a.x + bs.x - bd.x + bb.x;
        float v1 = a.y + bs.y - bd.y + bb.y;
        float v2 = a.z + bs.z - bd.z + bb.z;
        float v3 = a.w + bs.w - bd.w + bb.w;
        if (v0 > 0.f) atomicMax(po + c + 0, __float_as_int(v0));
        if (v1 > 0.f) atomicMax(po + c + 1, __float_as_int(v1));
        if (v2 > 0.f) atomicMax(po + c + 2, __float_as_int(v2));
        if (v3 > 0.f) atomicMax(po + c + 3, __float_as_int(v3));
    }
}

// ---------------------------------------------------------------------------
// conv1d(k=5,pad=2) + relu + maxpool(2) as GEMM with shifted-row A gather.
// X: [M, 256] (rows = bn*L + l), Wt: [1280, 256], Y: [M/2, 256]
template <int L>
__global__ __launch_bounds__(256, 2)
void convpool(const float* __restrict__ X, const float* __restrict__ Wt,
              const float* __restrict__ bias, float* __restrict__ Y) {
    __shared__ float As[16][128];
    __shared__ float Bs[16][128];
    int tid = threadIdx.x;
    int bm = blockIdx.y * 128;
    int bn = blockIdx.x * 128;
    int a_row = tid >> 2;
    int a_col = (tid & 3) << 2;
    int b_row = tid >> 5;
    int b_col = (tid & 31) << 2;
    int ty = tid >> 4, tx = tid & 15;
    float acc[8][8] = {};

    for (int k0 = 0; k0 < 1280; k0 += 16) {
        int kshift = (k0 >> 8) - 2;     // -2..2 (each 16-wide tile has one k)
        int i0 = k0 & 255;
#pragma unroll
        for (int rr = 0; rr < 2; rr++) {
            int rm = bm + a_row + rr * 64;
            int srow = rm + kshift;
            float4 v = make_float4(0.f, 0.f, 0.f, 0.f);
            if (srow >= 0 && (srow / L) == (rm / L))
                v = *(const float4*)(X + (size_t)srow * 256 + i0 + a_col);
            int row = a_row + rr * 64;
            As[a_col + 0][row] = v.x; As[a_col + 1][row] = v.y;
            As[a_col + 2][row] = v.z; As[a_col + 3][row] = v.w;
        }
#pragma unroll
        for (int rr = 0; rr < 2; rr++) {
            int row = b_row + rr * 8;
            *(float4*)&Bs[row][b_col] = *(const float4*)(Wt + (size_t)(k0 + row) * 256 + bn + b_col);
        }
        __syncthreads();
#pragma unroll
        for (int k = 0; k < 16; k++) {
            float ra[8], rb[8];
            *(float4*)&ra[0] = *(float4*)&As[k][ty * 8];
            *(float4*)&ra[4] = *(float4*)&As[k][ty * 8 + 4];
            *(float4*)&rb[0] = *(float4*)&Bs[k][tx * 8];
            *(float4*)&rb[4] = *(float4*)&Bs[k][tx * 8 + 4];
#pragma unroll
            for (int i = 0; i < 8; i++)
#pragma unroll
                for (int j = 0; j < 8; j++)
                    acc[i][j] += ra[i] * rb[j];
        }
        __syncthreads();
    }

    // epilogue: +bias, relu, pool adjacent row pairs (within this thread)
    int colbase = bn + tx * 8;
    float bj[8];
    *(float4*)&bj[0] = *(const float4*)(bias + colbase);
    *(float4*)&bj[4] = *(const float4*)(bias + colbase + 4);
#pragma unroll
    for (int p = 0; p < 4; p++) {
        int rm = bm + ty * 8 + 2 * p;
        int yrow = rm >> 1;
        float v[8];
#pragma unroll
        for (int j = 0; j < 8; j++) {
            float u0 = acc[2 * p][j] + bj[j];     u0 = u0 > 0.f ? u0 : 0.f;
            float u1 = acc[2 * p + 1][j] + bj[j]; u1 = u1 > 0.f ? u1 : 0.f;
            v[j] = u0 > u1 ? u0 : u1;
        }
        *(float4*)(Y + (size_t)yrow * 256 + colbase)     = *(float4*)&v[0];
        *(float4*)(Y + (size_t)yrow * 256 + colbase + 4) = *(float4*)&v[4];
    }
}

// ---------------------------------------------------------------------------
extern "C" void kernel_launch(void* const* d_in, const int* in_sizes, int n_in,
                              void* d_out, int out_size) {
    const float* data = (const float*)d_in[0];
    // d_in[1] all_ohs: unused in 'fast' path
    const int*   ei0  = (const int*)d_in[2];
    const int*   ei1  = (const int*)d_in[3];
    const float* W0   = (const float*)d_in[4];
    const float* b0   = (const float*)d_in[5];
    const float* Wc0  = (const float*)d_in[6];
    const float* bc0  = (const float*)d_in[7];
    const float* W1   = (const float*)d_in[8];
    const float* b1   = (const float*)d_in[9];
    const float* Wc1  = (const float*)d_in[10];
    const float* bc1  = (const float*)d_in[11];
    float* out = (float*)d_out;

    void* sp = nullptr;
    cudaGetSymbolAddress(&sp, g_scratch);
    float* S     = (float*)sp;
    float* x0    = S + OFF_X0;
    float* AB0   = S + OFF_AB0;
    float* out0  = S + OFF_OUT0;
    float* x1    = S + OFF_X1;
    float* AB1   = S + OFF_AB1;
    float* out1  = S + OFF_OUT1;
    float* Wcat0 = S + OFF_WCAT0;
    float* Wcat1 = S + OFF_WCAT1;
    float* Wt0   = S + OFF_WT0;
    float* Wt1   = S + OFF_WT1;

    prep_weights<<<3328, 256>>>(W0, W1, Wc0, Wc1, Wcat0, Wcat1, Wt0, Wt1);
    permute_in<<<(M0 * F_) / 256, 256>>>(data, x0);
    zero_kernel<<<SZ_OUT0 / 1024, 256>>>((float4*)out0);
    zero_kernel<<<SZ_OUT1 / 1024, 256>>>((float4*)out1);

    // layer 0
    sgemm128<<<dim3(4, M0 / 128), 256>>>(x0, Wcat0, AB0, 512, 128);
    edge_agg<<<E0 / 8, 256>>>(ei0, E0, AB0, b0, out0);
    convpool<128><<<dim3(2, M0 / 128), 256>>>(out0, Wt0, bc0, x1);

    // layer 1
    sgemm128<<<dim3(4, M1 / 128), 256>>>(x1, Wcat1, AB1, 512, 256);
    edge_agg<<<E1 / 8, 256>>>(ei1, E1, AB1, b1, out1);
    convpool<64><<<dim3(2, M1 / 128), 256>>>(out1, Wt1, bc1, out);
}

// round 2
// speedup vs baseline: 1.9589x; 1.9589x over previous
#include <cuda_runtime.h>
#include <cstdint>

// ---------------------------------------------------------------------------
// Encoder_35064113004946: 2x (EdgeConv -> Conv1d(k=5,pad=2)+ReLU+MaxPool1d(2))
//
// EdgeConv trick: cat[x_i, x_j - x_i] @ W = x_i @ W_top + (x_j - x_i) @ W_bot
//   => per-node A = X@W_top, B = X@W_bot; per-edge msg = relu(A[d]+B[s]-B[d]+b)
//   => segment_max == atomicMax(float-as-int) into 0-initialized out (msgs>=0)
// Conv1d+pool: GEMM over K = 5*256 with shifted-row A gather, relu+maxpool
//   fused in epilogue via shfl (pool partner row gid^1 lives in lane^4).
// GEMMs run on the tensor pipe: tf32 mma.sync.m16n8k8 (HMMA), fp32 accum.
// ---------------------------------------------------------------------------

#define T_      128
#define F_      128
#define H_      256
#define M0      32768          // B*N*T nodes, layer 0
#define E0      262144
#define M1      16384          // after pool /2
#define E1      131072

// scratch layout (floats)
#define OFF_X0     0
#define SZ_X0      (M0 * F_)
#define OFF_AB0    (OFF_X0 + SZ_X0)
#define SZ_AB0     (M0 * 512)
#define OFF_OUT0   (OFF_AB0 + SZ_AB0)
#define SZ_OUT0    (M0 * 256)
#define OFF_X1     (OFF_OUT0 + SZ_OUT0)
#define SZ_X1      (M1 * 256)
#define OFF_AB1    (OFF_X1 + SZ_X1)
#define SZ_AB1     (M1 * 512)
#define OFF_OUT1   (OFF_AB1 + SZ_AB1)
#define SZ_OUT1    (M1 * 256)
#define OFF_WCAT0  (OFF_OUT1 + SZ_OUT1)
#define SZ_WCAT0   (128 * 512)
#define OFF_WCAT1  (OFF_WCAT0 + SZ_WCAT0)
#define SZ_WCAT1   (256 * 512)
#define OFF_WT0    (OFF_WCAT1 + SZ_WCAT1)
#define SZ_WT      (1280 * 256)
#define OFF_WT1    (OFF_WT0 + SZ_WT)
#define SCRATCH_TOTAL (OFF_WT1 + SZ_WT)

__device__ float g_scratch[SCRATCH_TOTAL];

// ---------------------------------------------------------------------------
__device__ __forceinline__ unsigned f2tf32(float x) {
    unsigned r;
    asm("cvt.rna.tf32.f32 %0, %1;" : "=r"(r) : "f"(x));
    return r;
}

__device__ __forceinline__ void mma_tf32(float* d, const unsigned* a, const unsigned* b) {
    asm volatile(
        "mma.sync.aligned.m16n8k8.row.col.f32.tf32.tf32.f32 "
        "{%0,%1,%2,%3}, {%4,%5,%6,%7}, {%8,%9}, {%0,%1,%2,%3};\n"
        : "+f"(d[0]), "+f"(d[1]), "+f"(d[2]), "+f"(d[3])
        : "r"(a[0]), "r"(a[1]), "r"(a[2]), "r"(a[3]), "r"(b[0]), "r"(b[1]));
}

// ---------------------------------------------------------------------------
// input permute: data[T,B,N,F] -> x0[(b*32+n)*128 + t, f]
__global__ void permute_in(const float* __restrict__ data, float* __restrict__ x0) {
    int idx = blockIdx.x * 256 + threadIdx.x;
    int f    = idx & 127;
    int node = idx >> 7;
    int t    = node & 127;
    int bn   = node >> 7;
    int b    = bn >> 5;
    int n    = bn & 31;
    x0[idx] = data[(((t * 8 + b) * 32 + n) << 7) + f];
}

// ---------------------------------------------------------------------------
// weight prep: Wcat = [W_top | W_bot] (K x 512); Wt[(k*256+i)*256+o] = Wc[o,i,k]
__global__ void prep_weights(const float* __restrict__ W0, const float* __restrict__ W1,
                             const float* __restrict__ Wc0, const float* __restrict__ Wc1,
                             float* __restrict__ Wcat0, float* __restrict__ Wcat1,
                             float* __restrict__ Wt0, float* __restrict__ Wt1) {
    int idx = blockIdx.x * 256 + threadIdx.x;
    if (idx < 65536) {
        int f = idx >> 9, h = idx & 511;
        Wcat0[idx] = (h < 256) ? W0[f * 256 + h] : W0[(128 + f) * 256 + (h - 256)];
        return;
    }
    idx -= 65536;
    if (idx < 131072) {
        int i = idx >> 9, h = idx & 511;
        Wcat1[idx] = (h < 256) ? W1[i * 256 + h] : W1[(256 + i) * 256 + (h - 256)];
        return;
    }
    idx -= 131072;
    if (idx < 327680) {
        int kk = idx >> 8, o = idx & 255;
        int k = kk >> 8, i = kk & 255;
        Wt0[idx] = Wc0[(o * 256 + i) * 5 + k];
        return;
    }
    idx -= 327680;
    if (idx < 327680) {
        int kk = idx >> 8, o = idx & 255;
        int k = kk >> 8, i = kk & 255;
        Wt1[idx] = Wc1[(o * 256 + i) * 5 + k];
    }
}

// ---------------------------------------------------------------------------
__global__ void zero_kernel(float4* __restrict__ p) {
    p[blockIdx.x * 256 + threadIdx.x] = make_float4(0.f, 0.f, 0.f, 0.f);
}

// ---------------------------------------------------------------------------
// tf32 tensor-core SGEMM: C[M,N] = A[M,K] @ B[K,N]; M%128==0, N%128==0, K%16==0
// Block tile 128x128, 8 warps, warp tile 32x64 (2x8 of m16n8k8).
__global__ __launch_bounds__(256)
void sgemm_tf32(const float* __restrict__ A, const float* __restrict__ B,
                float* __restrict__ C, int N, int K) {
    __shared__ unsigned As[16][136];   // [k][m], stride 136 -> conflict-free frags
    __shared__ unsigned Bs[16][136];   // [k][n]
    int tid = threadIdx.x;
    int lane = tid & 31, wid = tid >> 5;
    int wm = wid & 3, wn = wid >> 2;
    int gid = lane >> 2, tg = lane & 3;
    int bm = blockIdx.y * 128, bn = blockIdx.x * 128;
    int arow = tid >> 2, acol = (tid & 3) << 2;
    int brow = tid >> 5, bcol = (tid & 31) << 2;
    float acc[2][8][4] = {};

    for (int k0 = 0; k0 < K; k0 += 16) {
#pragma unroll
        for (int rr = 0; rr < 2; rr++) {
            int row = arow + rr * 64;
            float4 v = *(const float4*)(A + (size_t)(bm + row) * K + k0 + acol);
            As[acol + 0][row] = f2tf32(v.x);
            As[acol + 1][row] = f2tf32(v.y);
            As[acol + 2][row] = f2tf32(v.z);
            As[acol + 3][row] = f2tf32(v.w);
        }
#pragma unroll
        for (int rr = 0; rr < 2; rr++) {
            int row = brow + rr * 8;
            float4 v = *(const float4*)(B + (size_t)(k0 + row) * N + bn + bcol);
            uint4 u = make_uint4(f2tf32(v.x), f2tf32(v.y), f2tf32(v.z), f2tf32(v.w));
            *(uint4*)&Bs[row][bcol] = u;
        }
        __syncthreads();
#pragma unroll
        for (int kk = 0; kk < 16; kk += 8) {
            unsigned a[2][4], b[8][2];
#pragma unroll
            for (int mi = 0; mi < 2; mi++) {
                int m0 = wm * 32 + mi * 16 + gid;
                a[mi][0] = As[kk + tg][m0];
                a[mi][1] = As[kk + tg][m0 + 8];
                a[mi][2] = As[kk + tg + 4][m0];
                a[mi][3] = As[kk + tg + 4][m0 + 8];
            }
#pragma unroll
            for (int ni = 0; ni < 8; ni++) {
                int n0 = wn * 64 + ni * 8 + gid;
                b[ni][0] = Bs[kk + tg][n0];
                b[ni][1] = Bs[kk + tg + 4][n0];
            }
#pragma unroll
            for (int mi = 0; mi < 2; mi++)
#pragma unroll
                for (int ni = 0; ni < 8; ni++)
                    mma_tf32(acc[mi][ni], a[mi], b[ni]);
        }
        __syncthreads();
    }
#pragma unroll
    for (int mi = 0; mi < 2; mi++) {
        int r0 = bm + wm * 32 + mi * 16 + gid;
#pragma unroll
        for (int ni = 0; ni < 8; ni++) {
            int c0 = bn + wn * 64 + ni * 8 + tg * 2;
            *(float2*)(C + (size_t)r0 * N + c0) = make_float2(acc[mi][ni][0], acc[mi][ni][1]);
            *(float2*)(C + (size_t)(r0 + 8) * N + c0) = make_float2(acc[mi][ni][2], acc[mi][ni][3]);
        }
    }
}

// ---------------------------------------------------------------------------
// edge aggregation: out[dst] = max(out[dst], relu(A[dst]+B[src]-B[dst]+bias))
__global__ void edge_agg(const int* __restrict__ ei, int E,
                         const float* __restrict__ AB,
                         const float* __restrict__ bias,
                         float* __restrict__ out) {
    int warp = (blockIdx.x * blockDim.x + threadIdx.x) >> 5;
    if (warp >= E) return;
    int lane = threadIdx.x & 31;
    int src = __ldg(ei + warp);
    int dst = __ldg(ei + E + warp);
    const float* basd = AB + (size_t)dst * 512;
    const float* bass = AB + (size_t)src * 512;
    int* po = (int*)(out + (size_t)dst * 256);
#pragma unroll
    for (int h = 0; h < 2; h++) {
        int c = lane * 4 + h * 128;
        float4 a  = *(const float4*)(basd + c);
        float4 bd = *(const float4*)(basd + 256 + c);
        float4 bs = *(const float4*)(bass + 256 + c);
        float4 bb = *(const float4*)(bias + c);
        float v0 = a.x + bs.x - bd.x + bb.x;
        float v1 = a.y + bs.y - bd.y + bb.y;
        float v2 = a.z + bs.z - bd.z + bb.z;
        float v3 = a.w + bs.w - bd.w + bb.w;
        if (v0 > 0.f) atomicMax(po + c + 0, __float_as_int(v0));
        if (v1 > 0.f) atomicMax(po + c + 1, __float_as_int(v1));
        if (v2 > 0.f) atomicMax(po + c + 2, __float_as_int(v2));
        if (v3 > 0.f) atomicMax(po + c + 3, __float_as_int(v3));
    }
}

// ---------------------------------------------------------------------------
// conv1d(k=5,pad=2)+relu+maxpool(2) as tf32 tensor-core GEMM.
// X: [M, 256] (rows = bn_node*L + l), Wt: [1280, 256], Y: [M/2, 256]
template <int L>
__global__ __launch_bounds__(256)
void convpool_tf32(const float* __restrict__ X, const float* __restrict__ Wt,
                   const float* __restrict__ bias, float* __restrict__ Y) {
    __shared__ unsigned As[16][136];
    __shared__ unsigned Bs[16][136];
    int tid = threadIdx.x;
    int lane = tid & 31, wid = tid >> 5;
    int wm = wid & 3, wn = wid >> 2;
    int gid = lane >> 2, tg = lane & 3;
    int bm = blockIdx.y * 128, bn = blockIdx.x * 128;
    int arow = tid >> 2, acol = (tid & 3) << 2;
    int brow = tid >> 5, bcol = (tid & 31) << 2;
    float acc[2][8][4] = {};

    for (int k0 = 0; k0 < 1280; k0 += 16) {
        int kshift = (k0 >> 8) - 2;
        int i0 = k0 & 255;
#pragma unroll
        for (int rr = 0; rr < 2; rr++) {
            int rm = bm + arow + rr * 64;
            int srow = rm + kshift;
            float4 v = make_float4(0.f, 0.f, 0.f, 0.f);
            if (srow >= 0 && (srow / L) == (rm / L))
                v = *(const float4*)(X + (size_t)srow * 256 + i0 + acol);
            int row = arow + rr * 64;
            As[acol + 0][row] = f2tf32(v.x);
            As[acol + 1][row] = f2tf32(v.y);
            As[acol + 2][row] = f2tf32(v.z);
            As[acol + 3][row] = f2tf32(v.w);
        }
#pragma unroll
        for (int rr = 0; rr < 2; rr++) {
            int row = brow + rr * 8;
            float4 v = *(const float4*)(Wt + (size_t)(k0 + row) * 256 + bn + bcol);
            uint4 u = make_uint4(f2tf32(v.x), f2tf32(v.y), f2tf32(v.z), f2tf32(v.w));
            *(uint4*)&Bs[row][bcol] = u;
        }
        __syncthreads();
#pragma unroll
        for (int kk = 0; kk < 16; kk += 8) {
            unsigned a[2][4], b[8][2];
#pragma unroll
            for (int mi = 0; mi < 2; mi++) {
                int m0 = wm * 32 + mi * 16 + gid;
                a[mi][0] = As[kk + tg][m0];
                a[mi][1] = As[kk + tg][m0 + 8];
                a[mi][2] = As[kk + tg + 4][m0];
                a[mi][3] = As[kk + tg + 4][m0 + 8];
            }
#pragma unroll
            for (int ni = 0; ni < 8; ni++) {
                int n0 = wn * 64 + ni * 8 + gid;
                b[ni][0] = Bs[kk + tg][n0];
                b[ni][1] = Bs[kk + tg + 4][n0];
            }
#pragma unroll
            for (int mi = 0; mi < 2; mi++)
#pragma unroll
                for (int ni = 0; ni < 8; ni++)
                    mma_tf32(acc[mi][ni], a[mi], b[ni]);
        }
        __syncthreads();
    }

    // epilogue: +bias, relu, pool rows (2r,2r+1); partner row is in lane^4
    bool write = (gid & 1) == 0;
#pragma unroll
    for (int mi = 0; mi < 2; mi++) {
        int rbase = bm + wm * 32 + mi * 16 + gid;
#pragma unroll
        for (int ni = 0; ni < 8; ni++) {
            int c0 = bn + wn * 64 + ni * 8 + tg * 2;
            float b0 = bias[c0], b1 = bias[c0 + 1];
            float u0 = fmaxf(acc[mi][ni][0] + b0, 0.f);
            float u1 = fmaxf(acc[mi][ni][1] + b1, 0.f);
            float u2 = fmaxf(acc[mi][ni][2] + b0, 0.f);
            float u3 = fmaxf(acc[mi][ni][3] + b1, 0.f);
            float p0 = fmaxf(u0, __shfl_xor_sync(0xffffffffu, u0, 4));
            float p1 = fmaxf(u1, __shfl_xor_sync(0xffffffffu, u1, 4));
            float p2 = fmaxf(u2, __shfl_xor_sync(0xffffffffu, u2, 4));
            float p3 = fmaxf(u3, __shfl_xor_sync(0xffffffffu, u3, 4));
            if (write) {
                *(float2*)(Y + (size_t)(rbase >> 1) * 256 + c0) = make_float2(p0, p1);
                *(float2*)(Y + (size_t)((rbase + 8) >> 1) * 256 + c0) = make_float2(p2, p3);
            }
        }
    }
}

// ---------------------------------------------------------------------------
extern "C" void kernel_launch(void* const* d_in, const int* in_sizes, int n_in,
                              void* d_out, int out_size) {
    const float* data = (const float*)d_in[0];
    const int*   ei0  = (const int*)d_in[2];
    const int*   ei1  = (const int*)d_in[3];
    const float* W0   = (const float*)d_in[4];
    const float* b0   = (const float*)d_in[5];
    const float* Wc0  = (const float*)d_in[6];
    const float* bc0  = (const float*)d_in[7];
    const float* W1   = (const float*)d_in[8];
    const float* b1   = (const float*)d_in[9];
    const float* Wc1  = (const float*)d_in[10];
    const float* bc1  = (const float*)d_in[11];
    float* out = (float*)d_out;

    void* sp = nullptr;
    cudaGetSymbolAddress(&sp, g_scratch);
    float* S     = (float*)sp;
    float* x0    = S + OFF_X0;
    float* AB0   = S + OFF_AB0;
    float* out0  = S + OFF_OUT0;
    float* x1    = S + OFF_X1;
    float* AB1   = S + OFF_AB1;
    float* out1  = S + OFF_OUT1;
    float* Wcat0 = S + OFF_WCAT0;
    float* Wcat1 = S + OFF_WCAT1;
    float* Wt0   = S + OFF_WT0;
    float* Wt1   = S + OFF_WT1;

    prep_weights<<<3328, 256>>>(W0, W1, Wc0, Wc1, Wcat0, Wcat1, Wt0, Wt1);
    permute_in<<<(M0 * F_) / 256, 256>>>(data, x0);
    zero_kernel<<<SZ_OUT0 / 1024, 256>>>((float4*)out0);
    zero_kernel<<<SZ_OUT1 / 1024, 256>>>((float4*)out1);

    // layer 0
    sgemm_tf32<<<dim3(4, M0 / 128), 256>>>(x0, Wcat0, AB0, 512, 128);
    edge_agg<<<E0 / 8, 256>>>(ei0, E0, AB0, b0, out0);
    convpool_tf32<128><<<dim3(2, M0 / 128), 256>>>(out0, Wt0, bc0, x1);

    // layer 1
    sgemm_tf32<<<dim3(4, M1 / 128), 256>>>(x1, Wcat1, AB1, 512, 256);
    edge_agg<<<E1 / 8, 256>>>(ei1, E1, AB1, b1, out1);
    convpool_tf32<64><<<dim3(2, M1 / 128), 256>>>(out1, Wt1, bc1, out);
}